// round 7
// baseline (speedup 1.0000x reference)
// RBF kernel regression: out[B,F] = exp(-||z-x||^2/2) @ alpha
// B=2048, N=100000, D=64, F=16, fp32.
// R4: raise arithmetic intensity. 8b x 8n per thread (128x128 tile, 256 thr),
//     fma.rn.f32x2 paired along n; z pre-scaled by log2e so epilogue is a
//     single ex2.approx; norms baked into accumulator init; es staged fp32 in
//     two 64-n half-waves to keep smem at 109KB -> 2 blocks/SM; phase B reads
//     es as float4 with broadcast alpha. Deterministic partials + reduce.
#include <cuda_runtime.h>

#define DD 64
#define FF 16
#define BT 128
#define NT 128
#define ZP 132   // zs/xs row pad (floats)
#define EP 68    // es row pad (half-tile 64 n)
#define NBX 64
#define MAXB 2048
#define MAXN 100224
#define LOG2E 1.4426950408889634f

__device__ float g_xsq[MAXN];
__device__ float g_zsq[MAXB];
__device__ float g_part[(size_t)NBX * MAXB * FF];

struct __align__(16) SmemT {
    float zs[DD][ZP];    // z tile, k-major, pre-scaled by log2e
    float xs[DD][ZP];    // x tile, k-major
    float es[BT][EP];    // exp tile, half-wave (64 n)
    float as[NT][FF];    // alpha tile
    float zsq[BT];       // 0.5*||z||^2*log2e
    float xsq[NT];       // 0.5*||x||^2*log2e
};

static __device__ __forceinline__ float2 ffma2(float2 a, float2 b, float2 c) {
    unsigned long long ra = *reinterpret_cast<unsigned long long*>(&a);
    unsigned long long rb = *reinterpret_cast<unsigned long long*>(&b);
    unsigned long long rc = *reinterpret_cast<unsigned long long*>(&c);
    unsigned long long rd;
    asm("fma.rn.f32x2 %0, %1, %2, %3;" : "=l"(rd) : "l"(ra), "l"(rb), "l"(rc));
    return *reinterpret_cast<float2*>(&rd);
}

static __device__ __forceinline__ float ex2f(float x) {
    float y;
    asm("ex2.approx.ftz.f32 %0, %1;" : "=f"(y) : "f"(x));
    return y;
}

__global__ void prep_norms(const float* __restrict__ z,
                           const float* __restrict__ x, int B, int N) {
    int i = blockIdx.x * blockDim.x + threadIdx.x;
    if (i < N) {
        const float4* p = reinterpret_cast<const float4*>(x + (size_t)i * DD);
        float s = 0.f;
#pragma unroll
        for (int q = 0; q < DD / 4; q++) {
            float4 v = p[q];
            s += v.x * v.x + v.y * v.y + v.z * v.z + v.w * v.w;
        }
        g_xsq[i] = 0.5f * s * LOG2E;
    } else if (i < N + B) {
        int b = i - N;
        const float4* p = reinterpret_cast<const float4*>(z + (size_t)b * DD);
        float s = 0.f;
#pragma unroll
        for (int q = 0; q < DD / 4; q++) {
            float4 v = p[q];
            s += v.x * v.x + v.y * v.y + v.z * v.z + v.w * v.w;
        }
        g_zsq[b] = 0.5f * s * LOG2E;
    }
}

// phase B over one 64-n half-wave: thread owns (b = t>>1, f-half)
static __device__ __forceinline__ void phaseB(const SmemT* s, int bb, int fh,
                                              int n_off, float2 oacc[4]) {
#pragma unroll 4
    for (int n4 = 0; n4 < 16; n4++) {
        float4 e4 = *reinterpret_cast<const float4*>(&s->es[bb][n4 * 4]);
        float ev[4] = {e4.x, e4.y, e4.z, e4.w};
#pragma unroll
        for (int jj = 0; jj < 4; jj++) {
            const float* ar = s->as[n_off + n4 * 4 + jj];
            float4 A0 = *reinterpret_cast<const float4*>(&ar[fh]);
            float4 A1 = *reinterpret_cast<const float4*>(&ar[fh + 4]);
            float2 e2 = make_float2(ev[jj], ev[jj]);
            oacc[0] = ffma2(e2, make_float2(A0.x, A0.y), oacc[0]);
            oacc[1] = ffma2(e2, make_float2(A0.z, A0.w), oacc[1]);
            oacc[2] = ffma2(e2, make_float2(A1.x, A1.y), oacc[2]);
            oacc[3] = ffma2(e2, make_float2(A1.z, A1.w), oacc[3]);
        }
    }
}

__global__ __launch_bounds__(256, 2) void rbf_main(
    const float* __restrict__ z, const float* __restrict__ x,
    const float* __restrict__ alpha, int B, int N, int ntiles) {
    extern __shared__ SmemT smem[];
    SmemT* s = smem;
    const int t = threadIdx.x;
    const int tx = t & 15;   // n direction (8 n each)
    const int ty = t >> 4;   // b direction (8 b each)
    const int b_base = blockIdx.y * BT;

    // ---- load z tile once: transpose [b][k] -> zs[k][b], scaled by log2e ----
#pragma unroll
    for (int r = 0; r < 8; r++) {
        int idx = t + r * 256;          // 0..2047
        int row = idx >> 4, q = idx & 15;
        float4 v = *reinterpret_cast<const float4*>(
            &z[(size_t)(b_base + row) * DD + q * 4]);
        s->zs[q * 4 + 0][row] = v.x * LOG2E;
        s->zs[q * 4 + 1][row] = v.y * LOG2E;
        s->zs[q * 4 + 2][row] = v.z * LOG2E;
        s->zs[q * 4 + 3][row] = v.w * LOG2E;
    }
    if (t < BT) s->zsq[t] = g_zsq[b_base + t];

    const int bb = t >> 1;
    const int fh = (t & 1) * 8;
    float2 oacc[4];
    oacc[0] = make_float2(0.f, 0.f); oacc[1] = make_float2(0.f, 0.f);
    oacc[2] = make_float2(0.f, 0.f); oacc[3] = make_float2(0.f, 0.f);

    for (int tile = blockIdx.x; tile < ntiles; tile += NBX) {
        const int n_base = tile * NT;
        __syncthreads();   // xs/as/es free
        // ---- x tile transpose, xsq, alpha ----
#pragma unroll
        for (int r = 0; r < 8; r++) {
            int idx = t + r * 256;      // 0..2047
            int nl = idx >> 4, q = idx & 15;
            int ng = n_base + nl;
            float4 v = make_float4(0.f, 0.f, 0.f, 0.f);
            if (ng < N)
                v = *reinterpret_cast<const float4*>(&x[(size_t)ng * DD + q * 4]);
            s->xs[q * 4 + 0][nl] = v.x;
            s->xs[q * 4 + 1][nl] = v.y;
            s->xs[q * 4 + 2][nl] = v.z;
            s->xs[q * 4 + 3][nl] = v.w;
        }
        if (t < NT) {
            int ng = n_base + t;
            s->xsq[t] = (ng < N) ? g_xsq[ng] : 1.0e30f;  // sentinel -> ex2 = 0
        }
#pragma unroll
        for (int r = 0; r < 2; r++) {
            int idx = t + r * 256;      // 0..511
            int nl = idx >> 2, c = (idx & 3) * 4;
            int ng = n_base + nl;
            float4 v = make_float4(0.f, 0.f, 0.f, 0.f);
            if (ng < N)
                v = *reinterpret_cast<const float4*>(&alpha[(size_t)ng * FF + c]);
            *reinterpret_cast<float4*>(&s->as[nl][c]) = v;
        }
        __syncthreads();

        // ---- phase A: acc = z.x*log2e - hz - hx (8b x 8n, f32x2 on n) ----
        float hz[8];
#pragma unroll
        for (int i = 0; i < 8; i++) hz[i] = s->zsq[ty * 8 + i];
        float4 h0 = *reinterpret_cast<const float4*>(&s->xsq[tx * 8]);
        float4 h1 = *reinterpret_cast<const float4*>(&s->xsq[tx * 8 + 4]);
        float hx[8] = {h0.x, h0.y, h0.z, h0.w, h1.x, h1.y, h1.z, h1.w};
        float2 acc[8][4];
#pragma unroll
        for (int i = 0; i < 8; i++)
#pragma unroll
            for (int j = 0; j < 4; j++)
                acc[i][j] = make_float2(-(hz[i] + hx[2 * j]),
                                        -(hz[i] + hx[2 * j + 1]));

#pragma unroll 8
        for (int k = 0; k < DD; k++) {
            float4 a0 = *reinterpret_cast<const float4*>(&s->zs[k][ty * 8]);
            float4 a1 = *reinterpret_cast<const float4*>(&s->zs[k][ty * 8 + 4]);
            float4 b0 = *reinterpret_cast<const float4*>(&s->xs[k][tx * 8]);
            float4 b1 = *reinterpret_cast<const float4*>(&s->xs[k][tx * 8 + 4]);
            float av[8] = {a0.x, a0.y, a0.z, a0.w, a1.x, a1.y, a1.z, a1.w};
            float2 bp[4];
            bp[0] = make_float2(b0.x, b0.y); bp[1] = make_float2(b0.z, b0.w);
            bp[2] = make_float2(b1.x, b1.y); bp[3] = make_float2(b1.z, b1.w);
#pragma unroll
            for (int i = 0; i < 8; i++) {
                float2 ad = make_float2(av[i], av[i]);
                acc[i][0] = ffma2(ad, bp[0], acc[i][0]);
                acc[i][1] = ffma2(ad, bp[1], acc[i][1]);
                acc[i][2] = ffma2(ad, bp[2], acc[i][2]);
                acc[i][3] = ffma2(ad, bp[3], acc[i][3]);
            }
        }
        // exp in place
#pragma unroll
        for (int i = 0; i < 8; i++)
#pragma unroll
            for (int j = 0; j < 4; j++) {
                acc[i][j].x = ex2f(acc[i][j].x);
                acc[i][j].y = ex2f(acc[i][j].y);
            }

        // ---- wave 1: threads tx<8 hold n 0..63; store es, run phase B ----
        const int col = (tx & 7) * 8;
        if (tx < 8) {
#pragma unroll
            for (int i = 0; i < 8; i++) {
                float4 v0 = make_float4(acc[i][0].x, acc[i][0].y,
                                        acc[i][1].x, acc[i][1].y);
                float4 v1 = make_float4(acc[i][2].x, acc[i][2].y,
                                        acc[i][3].x, acc[i][3].y);
                *reinterpret_cast<float4*>(&s->es[ty * 8 + i][col]) = v0;
                *reinterpret_cast<float4*>(&s->es[ty * 8 + i][col + 4]) = v1;
            }
        }
        __syncthreads();
        phaseB(s, bb, fh, 0, oacc);
        __syncthreads();
        // ---- wave 2: threads tx>=8 hold n 64..127 ----
        if (tx >= 8) {
#pragma unroll
            for (int i = 0; i < 8; i++) {
                float4 v0 = make_float4(acc[i][0].x, acc[i][0].y,
                                        acc[i][1].x, acc[i][1].y);
                float4 v1 = make_float4(acc[i][2].x, acc[i][2].y,
                                        acc[i][3].x, acc[i][3].y);
                *reinterpret_cast<float4*>(&s->es[ty * 8 + i][col]) = v0;
                *reinterpret_cast<float4*>(&s->es[ty * 8 + i][col + 4]) = v1;
            }
        }
        __syncthreads();
        phaseB(s, bb, fh, 64, oacc);
    }

    // deterministic partial write
    float* pp = &g_part[((size_t)blockIdx.x * MAXB + (b_base + bb)) * FF + fh];
    pp[0] = oacc[0].x; pp[1] = oacc[0].y;
    pp[2] = oacc[1].x; pp[3] = oacc[1].y;
    pp[4] = oacc[2].x; pp[5] = oacc[2].y;
    pp[6] = oacc[3].x; pp[7] = oacc[3].y;
}

__global__ void reduce_out(float* __restrict__ out, int B) {
    int i = blockIdx.x * blockDim.x + threadIdx.x;
    if (i >= B * FF) return;
    int b = i / FF, f = i % FF;
    float sum = 0.f;
#pragma unroll 8
    for (int c = 0; c < NBX; c++)
        sum += g_part[((size_t)c * MAXB + b) * FF + f];
    out[i] = sum;
}

extern "C" void kernel_launch(void* const* d_in, const int* in_sizes, int n_in,
                              void* d_out, int out_size) {
    const float* z = (const float*)d_in[0];
    const float* x = (const float*)d_in[1];
    const float* alpha = (const float*)d_in[2];
    int B = in_sizes[0] / DD;   // 2048
    int N = in_sizes[1] / DD;   // 100000

    prep_norms<<<(N + B + 255) / 256, 256>>>(z, x, B, N);

    int ntiles = (N + NT - 1) / NT;
    cudaFuncSetAttribute(rbf_main, cudaFuncAttributeMaxDynamicSharedMemorySize,
                         (int)sizeof(SmemT));
    dim3 grid(NBX, B / BT);
    rbf_main<<<grid, 256, sizeof(SmemT)>>>(z, x, alpha, B, N, ntiles);

    reduce_out<<<(B * FF + 255) / 256, 256>>>((float*)d_out, B);
}

// round 9
// speedup vs baseline: 1.0089x; 1.0089x over previous
// RBF kernel regression: out[B,F] = exp(-||z-x||^2/2) @ alpha
// B=2048, N=100000, D=64, F=16, fp32.
// R4: raise arithmetic intensity. 8b x 8n per thread (128x128 tile, 256 thr),
//     fma.rn.f32x2 paired along n; z pre-scaled by log2e so epilogue is a
//     single ex2.approx; norms baked into accumulator init; es staged fp32 in
//     two 64-n half-waves to keep smem at 109KB -> 2 blocks/SM; phase B reads
//     es as float4 with broadcast alpha. Deterministic partials + reduce.
#include <cuda_runtime.h>

#define DD 64
#define FF 16
#define BT 128
#define NT 128
#define ZP 132   // zs/xs row pad (floats)
#define EP 68    // es row pad (half-tile 64 n)
#define NBX 64
#define MAXB 2048
#define MAXN 100224
#define LOG2E 1.4426950408889634f

__device__ float g_xsq[MAXN];
__device__ float g_zsq[MAXB];
__device__ float g_part[(size_t)NBX * MAXB * FF];

struct __align__(16) SmemT {
    float zs[DD][ZP];    // z tile, k-major, pre-scaled by log2e
    float xs[DD][ZP];    // x tile, k-major
    float es[BT][EP];    // exp tile, half-wave (64 n)
    float as[NT][FF];    // alpha tile
    float zsq[BT];       // 0.5*||z||^2*log2e
    float xsq[NT];       // 0.5*||x||^2*log2e
};

static __device__ __forceinline__ float2 ffma2(float2 a, float2 b, float2 c) {
    unsigned long long ra = *reinterpret_cast<unsigned long long*>(&a);
    unsigned long long rb = *reinterpret_cast<unsigned long long*>(&b);
    unsigned long long rc = *reinterpret_cast<unsigned long long*>(&c);
    unsigned long long rd;
    asm("fma.rn.f32x2 %0, %1, %2, %3;" : "=l"(rd) : "l"(ra), "l"(rb), "l"(rc));
    return *reinterpret_cast<float2*>(&rd);
}

static __device__ __forceinline__ float ex2f(float x) {
    float y;
    asm("ex2.approx.ftz.f32 %0, %1;" : "=f"(y) : "f"(x));
    return y;
}

__global__ void prep_norms(const float* __restrict__ z,
                           const float* __restrict__ x, int B, int N) {
    int i = blockIdx.x * blockDim.x + threadIdx.x;
    if (i < N) {
        const float4* p = reinterpret_cast<const float4*>(x + (size_t)i * DD);
        float s = 0.f;
#pragma unroll
        for (int q = 0; q < DD / 4; q++) {
            float4 v = p[q];
            s += v.x * v.x + v.y * v.y + v.z * v.z + v.w * v.w;
        }
        g_xsq[i] = 0.5f * s * LOG2E;
    } else if (i < N + B) {
        int b = i - N;
        const float4* p = reinterpret_cast<const float4*>(z + (size_t)b * DD);
        float s = 0.f;
#pragma unroll
        for (int q = 0; q < DD / 4; q++) {
            float4 v = p[q];
            s += v.x * v.x + v.y * v.y + v.z * v.z + v.w * v.w;
        }
        g_zsq[b] = 0.5f * s * LOG2E;
    }
}

// phase B over one 64-n half-wave: thread owns (b = t>>1, f-half)
static __device__ __forceinline__ void phaseB(const SmemT* s, int bb, int fh,
                                              int n_off, float2 oacc[4]) {
#pragma unroll 4
    for (int n4 = 0; n4 < 16; n4++) {
        float4 e4 = *reinterpret_cast<const float4*>(&s->es[bb][n4 * 4]);
        float ev[4] = {e4.x, e4.y, e4.z, e4.w};
#pragma unroll
        for (int jj = 0; jj < 4; jj++) {
            const float* ar = s->as[n_off + n4 * 4 + jj];
            float4 A0 = *reinterpret_cast<const float4*>(&ar[fh]);
            float4 A1 = *reinterpret_cast<const float4*>(&ar[fh + 4]);
            float2 e2 = make_float2(ev[jj], ev[jj]);
            oacc[0] = ffma2(e2, make_float2(A0.x, A0.y), oacc[0]);
            oacc[1] = ffma2(e2, make_float2(A0.z, A0.w), oacc[1]);
            oacc[2] = ffma2(e2, make_float2(A1.x, A1.y), oacc[2]);
            oacc[3] = ffma2(e2, make_float2(A1.z, A1.w), oacc[3]);
        }
    }
}

__global__ __launch_bounds__(256, 2) void rbf_main(
    const float* __restrict__ z, const float* __restrict__ x,
    const float* __restrict__ alpha, int B, int N, int ntiles) {
    extern __shared__ SmemT smem[];
    SmemT* s = smem;
    const int t = threadIdx.x;
    const int tx = t & 15;   // n direction (8 n each)
    const int ty = t >> 4;   // b direction (8 b each)
    const int b_base = blockIdx.y * BT;

    // ---- load z tile once: transpose [b][k] -> zs[k][b], scaled by log2e ----
#pragma unroll
    for (int r = 0; r < 8; r++) {
        int idx = t + r * 256;          // 0..2047
        int row = idx >> 4, q = idx & 15;
        float4 v = *reinterpret_cast<const float4*>(
            &z[(size_t)(b_base + row) * DD + q * 4]);
        s->zs[q * 4 + 0][row] = v.x * LOG2E;
        s->zs[q * 4 + 1][row] = v.y * LOG2E;
        s->zs[q * 4 + 2][row] = v.z * LOG2E;
        s->zs[q * 4 + 3][row] = v.w * LOG2E;
    }
    if (t < BT) s->zsq[t] = g_zsq[b_base + t];

    const int bb = t >> 1;
    const int fh = (t & 1) * 8;
    float2 oacc[4];
    oacc[0] = make_float2(0.f, 0.f); oacc[1] = make_float2(0.f, 0.f);
    oacc[2] = make_float2(0.f, 0.f); oacc[3] = make_float2(0.f, 0.f);

    for (int tile = blockIdx.x; tile < ntiles; tile += NBX) {
        const int n_base = tile * NT;
        __syncthreads();   // xs/as/es free
        // ---- x tile transpose, xsq, alpha ----
#pragma unroll
        for (int r = 0; r < 8; r++) {
            int idx = t + r * 256;      // 0..2047
            int nl = idx >> 4, q = idx & 15;
            int ng = n_base + nl;
            float4 v = make_float4(0.f, 0.f, 0.f, 0.f);
            if (ng < N)
                v = *reinterpret_cast<const float4*>(&x[(size_t)ng * DD + q * 4]);
            s->xs[q * 4 + 0][nl] = v.x;
            s->xs[q * 4 + 1][nl] = v.y;
            s->xs[q * 4 + 2][nl] = v.z;
            s->xs[q * 4 + 3][nl] = v.w;
        }
        if (t < NT) {
            int ng = n_base + t;
            s->xsq[t] = (ng < N) ? g_xsq[ng] : 1.0e30f;  // sentinel -> ex2 = 0
        }
#pragma unroll
        for (int r = 0; r < 2; r++) {
            int idx = t + r * 256;      // 0..511
            int nl = idx >> 2, c = (idx & 3) * 4;
            int ng = n_base + nl;
            float4 v = make_float4(0.f, 0.f, 0.f, 0.f);
            if (ng < N)
                v = *reinterpret_cast<const float4*>(&alpha[(size_t)ng * FF + c]);
            *reinterpret_cast<float4*>(&s->as[nl][c]) = v;
        }
        __syncthreads();

        // ---- phase A: acc = z.x*log2e - hz - hx (8b x 8n, f32x2 on n) ----
        float hz[8];
#pragma unroll
        for (int i = 0; i < 8; i++) hz[i] = s->zsq[ty * 8 + i];
        float4 h0 = *reinterpret_cast<const float4*>(&s->xsq[tx * 8]);
        float4 h1 = *reinterpret_cast<const float4*>(&s->xsq[tx * 8 + 4]);
        float hx[8] = {h0.x, h0.y, h0.z, h0.w, h1.x, h1.y, h1.z, h1.w};
        float2 acc[8][4];
#pragma unroll
        for (int i = 0; i < 8; i++)
#pragma unroll
            for (int j = 0; j < 4; j++)
                acc[i][j] = make_float2(-(hz[i] + hx[2 * j]),
                                        -(hz[i] + hx[2 * j + 1]));

#pragma unroll 8
        for (int k = 0; k < DD; k++) {
            float4 a0 = *reinterpret_cast<const float4*>(&s->zs[k][ty * 8]);
            float4 a1 = *reinterpret_cast<const float4*>(&s->zs[k][ty * 8 + 4]);
            float4 b0 = *reinterpret_cast<const float4*>(&s->xs[k][tx * 8]);
            float4 b1 = *reinterpret_cast<const float4*>(&s->xs[k][tx * 8 + 4]);
            float av[8] = {a0.x, a0.y, a0.z, a0.w, a1.x, a1.y, a1.z, a1.w};
            float2 bp[4];
            bp[0] = make_float2(b0.x, b0.y); bp[1] = make_float2(b0.z, b0.w);
            bp[2] = make_float2(b1.x, b1.y); bp[3] = make_float2(b1.z, b1.w);
#pragma unroll
            for (int i = 0; i < 8; i++) {
                float2 ad = make_float2(av[i], av[i]);
                acc[i][0] = ffma2(ad, bp[0], acc[i][0]);
                acc[i][1] = ffma2(ad, bp[1], acc[i][1]);
                acc[i][2] = ffma2(ad, bp[2], acc[i][2]);
                acc[i][3] = ffma2(ad, bp[3], acc[i][3]);
            }
        }
        // exp in place
#pragma unroll
        for (int i = 0; i < 8; i++)
#pragma unroll
            for (int j = 0; j < 4; j++) {
                acc[i][j].x = ex2f(acc[i][j].x);
                acc[i][j].y = ex2f(acc[i][j].y);
            }

        // ---- wave 1: threads tx<8 hold n 0..63; store es, run phase B ----
        const int col = (tx & 7) * 8;
        if (tx < 8) {
#pragma unroll
            for (int i = 0; i < 8; i++) {
                float4 v0 = make_float4(acc[i][0].x, acc[i][0].y,
                                        acc[i][1].x, acc[i][1].y);
                float4 v1 = make_float4(acc[i][2].x, acc[i][2].y,
                                        acc[i][3].x, acc[i][3].y);
                *reinterpret_cast<float4*>(&s->es[ty * 8 + i][col]) = v0;
                *reinterpret_cast<float4*>(&s->es[ty * 8 + i][col + 4]) = v1;
            }
        }
        __syncthreads();
        phaseB(s, bb, fh, 0, oacc);
        __syncthreads();
        // ---- wave 2: threads tx>=8 hold n 64..127 ----
        if (tx >= 8) {
#pragma unroll
            for (int i = 0; i < 8; i++) {
                float4 v0 = make_float4(acc[i][0].x, acc[i][0].y,
                                        acc[i][1].x, acc[i][1].y);
                float4 v1 = make_float4(acc[i][2].x, acc[i][2].y,
                                        acc[i][3].x, acc[i][3].y);
                *reinterpret_cast<float4*>(&s->es[ty * 8 + i][col]) = v0;
                *reinterpret_cast<float4*>(&s->es[ty * 8 + i][col + 4]) = v1;
            }
        }
        __syncthreads();
        phaseB(s, bb, fh, 64, oacc);
    }

    // deterministic partial write
    float* pp = &g_part[((size_t)blockIdx.x * MAXB + (b_base + bb)) * FF + fh];
    pp[0] = oacc[0].x; pp[1] = oacc[0].y;
    pp[2] = oacc[1].x; pp[3] = oacc[1].y;
    pp[4] = oacc[2].x; pp[5] = oacc[2].y;
    pp[6] = oacc[3].x; pp[7] = oacc[3].y;
}

__global__ void reduce_out(float* __restrict__ out, int B) {
    int i = blockIdx.x * blockDim.x + threadIdx.x;
    if (i >= B * FF) return;
    int b = i / FF, f = i % FF;
    float sum = 0.f;
#pragma unroll 8
    for (int c = 0; c < NBX; c++)
        sum += g_part[((size_t)c * MAXB + b) * FF + f];
    out[i] = sum;
}

extern "C" void kernel_launch(void* const* d_in, const int* in_sizes, int n_in,
                              void* d_out, int out_size) {
    const float* z = (const float*)d_in[0];
    const float* x = (const float*)d_in[1];
    const float* alpha = (const float*)d_in[2];
    int B = in_sizes[0] / DD;   // 2048
    int N = in_sizes[1] / DD;   // 100000

    prep_norms<<<(N + B + 255) / 256, 256>>>(z, x, B, N);

    int ntiles = (N + NT - 1) / NT;
    cudaFuncSetAttribute(rbf_main, cudaFuncAttributeMaxDynamicSharedMemorySize,
                         (int)sizeof(SmemT));
    dim3 grid(NBX, B / BT);
    rbf_main<<<grid, 256, sizeof(SmemT)>>>(z, x, alpha, B, N, ntiles);

    reduce_out<<<(B * FF + 255) / 256, 256>>>((float*)d_out, B);
}

// round 12
// speedup vs baseline: 2.7131x; 2.6891x over previous
// RBF regression out[B,F] = exp(-||z-x||^2/2) @ alpha.
// mma.sync (legacy HMMA, base sm_103-compatible) bf16 split-precision Gram
// GEMM (zh*xh + zh*xl + zl*xh, fp32 accum), -hz folded into accumulator init,
// z pre-scaled by log2e so epilogue is FADD + ex2.approx; K@alpha second GEMM
// in registers with fma.rn.f32x2 partials held across tiles; quad-shuffle
// reduction; cp.async 2-stage pipeline. Deterministic slabs + reduce.
#include <cuda_runtime.h>
#include <cuda_bf16.h>
#include <cstdint>

#define DD 64
#define FF 16
#define MT 128
#define NTL 128
#define NCH 37
#define MBLK 16
#define NSLAB (NCH * 2)
#define MAXB 2048
#define MAXN 100096
#define LOG2E 1.4426950408889634f

typedef unsigned long long ull;

__device__ __align__(16) __nv_bfloat16 g_zh[MAXB * DD];
__device__ __align__(16) __nv_bfloat16 g_zl[MAXB * DD];
__device__ __align__(16) __nv_bfloat16 g_xh[(size_t)MAXN * DD];
__device__ __align__(16) __nv_bfloat16 g_xl[(size_t)MAXN * DD];
__device__ float g_hz[MAXB];
__device__ __align__(16) float g_hx[MAXN];
__device__ __align__(16) float g_part[(size_t)NSLAB * MAXB * FF];

// smem layout (bytes)
#define SM_ZH 0
#define SM_ZL 16384
#define SM_X  32768            // per buf 32KB: xh, then xl at +16384
#define SM_AL 98304            // per buf 10240 (128 rows x 80B padded)
#define SM_HX 118784           // per buf 512
#define SM_TOT 119808

static __device__ __forceinline__ uint32_t smem_u32(const void* p) {
    uint32_t a;
    asm("{ .reg .u64 t; cvta.to.shared.u64 t, %1; cvt.u32.u64 %0, t; }"
        : "=r"(a) : "l"(p));
    return a;
}
static __device__ __forceinline__ uint32_t swz(uint32_t o) {
    return o ^ ((o >> 3) & 0x70);
}
static __device__ __forceinline__ float ex2f(float x) {
    float y;
    asm("ex2.approx.ftz.f32 %0, %1;" : "=f"(y) : "f"(x));
    return y;
}
static __device__ __forceinline__ ull pack2(float e) {
    ull r;
    asm("mov.b64 %0, {%1, %1};" : "=l"(r) : "f"(e));
    return r;
}
static __device__ __forceinline__ void fma2(ull& acc, ull a, ull b) {
    asm("fma.rn.f32x2 %0, %1, %2, %0;" : "+l"(acc) : "l"(a), "l"(b));
}
static __device__ __forceinline__ void ldm4(uint32_t a, uint32_t r[4]) {
    asm volatile("ldmatrix.sync.aligned.m8n8.x4.shared.b16 {%0,%1,%2,%3}, [%4];"
                 : "=r"(r[0]), "=r"(r[1]), "=r"(r[2]), "=r"(r[3]) : "r"(a));
}
static __device__ __forceinline__ void mma16816(float c[4], const uint32_t a[4],
                                                const uint32_t b0, const uint32_t b1) {
    asm volatile(
        "mma.sync.aligned.m16n8k16.row.col.f32.bf16.bf16.f32 "
        "{%0,%1,%2,%3}, {%4,%5,%6,%7}, {%8,%9}, {%0,%1,%2,%3};"
        : "+f"(c[0]), "+f"(c[1]), "+f"(c[2]), "+f"(c[3])
        : "r"(a[0]), "r"(a[1]), "r"(a[2]), "r"(a[3]), "r"(b0), "r"(b1));
}
static __device__ __forceinline__ void cpa16(uint32_t dst, const void* src, int sz) {
    asm volatile("cp.async.cg.shared.global [%0], [%1], 16, %2;"
                 :: "r"(dst), "l"(src), "r"(sz) : "memory");
}
#define CP_COMMIT() asm volatile("cp.async.commit_group;" ::: "memory")
#define CP_WAIT1()  asm volatile("cp.async.wait_group 1;" ::: "memory")
#define CP_WAIT0()  asm volatile("cp.async.wait_group 0;" ::: "memory")

// ---------- prep: bf16 hi/lo splits + log2e-scaled half-norms ----------
__global__ void prep_split(const float* __restrict__ z,
                           const float* __restrict__ x, int B, int N) {
    int i = blockIdx.x * blockDim.x + threadIdx.x;
    if (i < N) {
        const float4* p = reinterpret_cast<const float4*>(x + (size_t)i * DD);
        float s = 0.f;
#pragma unroll
        for (int q = 0; q < DD / 4; q++) {
            float4 v = p[q];
            s += v.x * v.x + v.y * v.y + v.z * v.z + v.w * v.w;
            float vv[4] = {v.x, v.y, v.z, v.w};
            __nv_bfloat16 h[4], l[4];
#pragma unroll
            for (int e = 0; e < 4; e++) {
                h[e] = __float2bfloat16(vv[e]);
                l[e] = __float2bfloat16(vv[e] - __bfloat162float(h[e]));
            }
            *reinterpret_cast<uint2*>(g_xh + (size_t)i * DD + q * 4) =
                *reinterpret_cast<uint2*>(h);
            *reinterpret_cast<uint2*>(g_xl + (size_t)i * DD + q * 4) =
                *reinterpret_cast<uint2*>(l);
        }
        g_hx[i] = 0.5f * s * LOG2E;
    } else if (i < N + B) {
        int b = i - N;
        const float4* p = reinterpret_cast<const float4*>(z + (size_t)b * DD);
        float s = 0.f;
#pragma unroll
        for (int q = 0; q < DD / 4; q++) {
            float4 v = p[q];
            s += v.x * v.x + v.y * v.y + v.z * v.z + v.w * v.w;
            float vv[4] = {v.x * LOG2E, v.y * LOG2E, v.z * LOG2E, v.w * LOG2E};
            __nv_bfloat16 h[4], l[4];
#pragma unroll
            for (int e = 0; e < 4; e++) {
                h[e] = __float2bfloat16(vv[e]);
                l[e] = __float2bfloat16(vv[e] - __bfloat162float(h[e]));
            }
            *reinterpret_cast<uint2*>(g_zh + (size_t)b * DD + q * 4) =
                *reinterpret_cast<uint2*>(h);
            *reinterpret_cast<uint2*>(g_zl + (size_t)b * DD + q * 4) =
                *reinterpret_cast<uint2*>(l);
        }
        g_hz[b] = 0.5f * s * LOG2E;
    }
}

// ---------- per-tile loads (cp.async) ----------
static __device__ __forceinline__ void load_tile(uint32_t su, const float* alpha,
                                                 int buf, int nb, int t, int N) {
    uint32_t xh_b = su + SM_X + buf * 32768;
    uint32_t xl_b = xh_b + 16384;
#pragma unroll
    for (int r4 = 0; r4 < 4; r4++) {
        int i = t + r4 * 256;
        int r = i >> 3, c = i & 7;
        int g = nb + r;
        int sz = g < N ? 16 : 0;
        size_t gi = (size_t)(g < N ? g : 0) * DD + c * 8;
        cpa16(xh_b + swz(r * 128 + c * 16), g_xh + gi, sz);
        cpa16(xl_b + swz(r * 128 + c * 16), g_xl + gi, sz);
    }
    uint32_t al_b = su + SM_AL + buf * 10240;
#pragma unroll
    for (int r2 = 0; r2 < 2; r2++) {
        int i = t + r2 * 256;
        int n = i >> 2, c = i & 3;
        int g = nb + n;
        int sz = g < N ? 16 : 0;
        cpa16(al_b + n * 80 + c * 16,
              alpha + (size_t)(g < N ? g : 0) * FF + c * 4, sz);
    }
    if (t < 32) {
        int pos = nb + t * 4;
        int rem = N - pos;
        int sz = rem >= 4 ? 16 : (rem > 0 ? rem * 4 : 0);
        cpa16(su + SM_HX + buf * 512 + t * 16, g_hx + (pos < N ? pos : 0), sz);
    }
}

__global__ __launch_bounds__(256, 1) void rbf_main(
    const float* __restrict__ alpha, int N, int ntiles) {
    extern __shared__ char sm[];
    const uint32_t su = smem_u32(sm);
    const int t = threadIdx.x, lane = t & 31, wid = t >> 5;
    const int wm = wid & 3, wn = wid >> 2;
    const int chunk = blockIdx.x, mb = blockIdx.y * MT;
    const int tc = (ntiles - chunk + NCH - 1) / NCH;
    const int g8 = lane >> 2;

    // z tiles (once), SW128 swizzled
#pragma unroll
    for (int r4 = 0; r4 < 4; r4++) {
        int i = t + r4 * 256;
        int r = i >> 3, c = i & 7;
        *(uint4*)(sm + SM_ZH + swz(r * 128 + c * 16)) =
            *(const uint4*)(g_zh + (size_t)(mb + r) * DD + c * 8);
        *(uint4*)(sm + SM_ZL + swz(r * 128 + c * 16)) =
            *(const uint4*)(g_zl + (size_t)(mb + r) * DD + c * 8);
    }

    float nhz[4];
#pragma unroll
    for (int mm = 0; mm < 4; mm++)
        nhz[mm] = -g_hz[mb + wm * 32 + (mm >> 1) * 16 + (mm & 1) * 8 + g8];

    // ldmatrix lane addressing (pure bit math; swizzle = XOR of lg<<4)
    const int lg = lane & 7, sel = lane >> 3;
    const uint32_t xr = (uint32_t)lg << 4;
    const uint32_t a_row = ((sel & 1) << 3) + lg;
    const uint32_t a_kx = (uint32_t)(sel >> 1) << 4;
    const uint32_t b_row = ((sel >> 1) << 3) + lg;
    const uint32_t b_kx = (uint32_t)(sel & 1) << 4;
    uint32_t abase_h[2], abase_l[2];
#pragma unroll
    for (int mi = 0; mi < 2; mi++) {
        uint32_t ro = (wm * 32 + mi * 16 + a_row) * 128;
        abase_h[mi] = su + SM_ZH + ro;
        abase_l[mi] = su + SM_ZL + ro;
    }

    ull o[4][8];
#pragma unroll
    for (int mm = 0; mm < 4; mm++)
#pragma unroll
        for (int fp = 0; fp < 8; fp++) o[mm][fp] = 0ull;

    // cp.async prologue
    load_tile(su, alpha, 0, chunk * NTL, t, N);
    CP_COMMIT();
    if (tc > 1) {
        load_tile(su, alpha, 1, (chunk + NCH) * NTL, t, N);
        CP_COMMIT();
    }

    for (int j = 0; j < tc; j++) {
        const int bi = j & 1;
        if (j + 1 < tc) CP_WAIT1(); else CP_WAIT0();
        __syncthreads();

        // ---- Gram tile via mma.sync, acc init = -hz ----
        float acc[2][8][4];
#pragma unroll
        for (int mi = 0; mi < 2; mi++)
#pragma unroll
            for (int ni = 0; ni < 8; ni++) {
                acc[mi][ni][0] = nhz[2 * mi];
                acc[mi][ni][1] = nhz[2 * mi];
                acc[mi][ni][2] = nhz[2 * mi + 1];
                acc[mi][ni][3] = nhz[2 * mi + 1];
            }
        const uint32_t xh_b = su + SM_X + bi * 32768;
        const uint32_t xl_b = xh_b + 16384;
        uint32_t bbase_h[4], bbase_l[4];
#pragma unroll
        for (int q = 0; q < 4; q++) {
            uint32_t ro = (wn * 64 + q * 16 + b_row) * 128;
            bbase_h[q] = xh_b + ro;
            bbase_l[q] = xl_b + ro;
        }
#pragma unroll
        for (int ks = 0; ks < 4; ks++) {
            const uint32_t kxa = ((uint32_t)(ks * 32) + a_kx) ^ xr;
            const uint32_t kxb = ((uint32_t)(ks * 32) + b_kx) ^ xr;
            uint32_t ah[2][4], al[2][4];
            ldm4(abase_h[0] + kxa, ah[0]);
            ldm4(abase_h[1] + kxa, ah[1]);
            ldm4(abase_l[0] + kxa, al[0]);
            ldm4(abase_l[1] + kxa, al[1]);
#pragma unroll
            for (int q = 0; q < 4; q++) {
                uint32_t bh4[4], bl4[4];
                ldm4(bbase_h[q] + kxb, bh4);
                ldm4(bbase_l[q] + kxb, bl4);
#pragma unroll
                for (int h = 0; h < 2; h++) {
                    const int ni = 2 * q + h;
#pragma unroll
                    for (int mi = 0; mi < 2; mi++) {
                        mma16816(acc[mi][ni], ah[mi], bh4[2 * h], bh4[2 * h + 1]);
                        mma16816(acc[mi][ni], ah[mi], bl4[2 * h], bl4[2 * h + 1]);
                        mma16816(acc[mi][ni], al[mi], bh4[2 * h], bh4[2 * h + 1]);
                    }
                }
            }
        }

        // ---- epilogue: exp + K@alpha into register partials ----
        const float* hxp = (const float*)(sm + SM_HX + bi * 512);
        const char* alp = sm + SM_AL + bi * 10240;
#pragma unroll
        for (int ni = 0; ni < 8; ni++) {
#pragma unroll
            for (int jj = 0; jj < 2; jj++) {
                const int nl = wn * 64 + ni * 8 + (lane & 3) * 2 + jj;
                const float nh = hxp[nl];
                const ulonglong2* ar = (const ulonglong2*)(alp + nl * 80);
                ulonglong2 p0 = ar[0], p1 = ar[1], p2 = ar[2], p3 = ar[3];
#pragma unroll
                for (int mi = 0; mi < 2; mi++) {
                    float e0 = ex2f(acc[mi][ni][jj] - nh);
                    float e1 = ex2f(acc[mi][ni][2 + jj] - nh);
                    ull e20 = pack2(e0), e21 = pack2(e1);
                    ull* o0 = o[2 * mi];
                    ull* o1 = o[2 * mi + 1];
                    fma2(o0[0], e20, p0.x); fma2(o0[1], e20, p0.y);
                    fma2(o0[2], e20, p1.x); fma2(o0[3], e20, p1.y);
                    fma2(o0[4], e20, p2.x); fma2(o0[5], e20, p2.y);
                    fma2(o0[6], e20, p3.x); fma2(o0[7], e20, p3.y);
                    fma2(o1[0], e21, p0.x); fma2(o1[1], e21, p0.y);
                    fma2(o1[2], e21, p1.x); fma2(o1[3], e21, p1.y);
                    fma2(o1[4], e21, p2.x); fma2(o1[5], e21, p2.y);
                    fma2(o1[6], e21, p3.x); fma2(o1[7], e21, p3.y);
                }
            }
        }
        __syncthreads();
        if (j + 2 < tc) {
            load_tile(su, alpha, bi, (chunk + (j + 2) * NCH) * NTL, t, N);
            CP_COMMIT();
        }
    }

    // quad reduction (lanes 4g..4g+3 hold disjoint n slices of same m rows)
    float red[64];
#pragma unroll
    for (int mm = 0; mm < 4; mm++)
#pragma unroll
        for (int fp = 0; fp < 8; fp++) {
            ull v = o[mm][fp];
            float x = __uint_as_float((uint32_t)v);
            float y = __uint_as_float((uint32_t)(v >> 32));
            x += __shfl_xor_sync(0xffffffffu, x, 1);
            x += __shfl_xor_sync(0xffffffffu, x, 2);
            y += __shfl_xor_sync(0xffffffffu, y, 1);
            y += __shfl_xor_sync(0xffffffffu, y, 2);
            red[mm * 16 + fp * 2] = x;
            red[mm * 16 + fp * 2 + 1] = y;
        }
    if ((lane & 3) == 0) {
        const int slab = chunk * 2 + wn;
#pragma unroll
        for (int mm = 0; mm < 4; mm++) {
            int m = mb + wm * 32 + (mm >> 1) * 16 + (mm & 1) * 8 + g8;
            float* pp = g_part + ((size_t)slab * MAXB + m) * FF;
#pragma unroll
            for (int q = 0; q < 4; q++)
                *(float4*)(pp + q * 4) =
                    make_float4(red[mm * 16 + q * 4], red[mm * 16 + q * 4 + 1],
                                red[mm * 16 + q * 4 + 2], red[mm * 16 + q * 4 + 3]);
        }
    }
}

__global__ void reduce_out(float* __restrict__ out, int B) {
    int i = blockIdx.x * blockDim.x + threadIdx.x;
    if (i >= B * FF) return;
    float s = 0.f;
#pragma unroll
    for (int c = 0; c < NSLAB; c++)
        s += g_part[(size_t)c * MAXB * FF + i];
    out[i] = s;
}

extern "C" void kernel_launch(void* const* d_in, const int* in_sizes, int n_in,
                              void* d_out, int out_size) {
    const float* z = (const float*)d_in[0];
    const float* x = (const float*)d_in[1];
    const float* alpha = (const float*)d_in[2];
    int B = in_sizes[0] / DD;   // 2048
    int N = in_sizes[1] / DD;   // 100000

    prep_split<<<(N + B + 255) / 256, 256>>>(z, x, B, N);

    int ntiles = (N + NTL - 1) / NTL;   // 782
    cudaFuncSetAttribute(rbf_main, cudaFuncAttributeMaxDynamicSharedMemorySize,
                         SM_TOT);
    rbf_main<<<dim3(NCH, MBLK), 256, SM_TOT>>>(alpha, N, ntiles);

    reduce_out<<<(B * FF + 255) / 256, 256>>>((float*)d_out, B);
}